// round 10
// baseline (speedup 1.0000x reference)
#include <cuda_runtime.h>
#include <cuda_bf16.h>
#include <cstdint>

// ---------------- problem constants ----------------
#define NB    32          // batch
#define CC    128         // cell channels
#define CIN   512         // input channels
#define HW    1024        // 32*32
#define PLANE (CC*HW)     // 131072 per (batch, state)
#define NBPLANE (NB*PLANE)
#define NMIX  14
#define BNS   0.9999950000374997f   // 1/sqrt(1+1e-5)
#define WSZ   (NMIX*CC*CC)          // 229376 per weight set

// ---------------- device scratch (static, allocation-free) ----------------
__device__ __align__(16) float g_s0[NBPLANE];
__device__ __align__(16) float g_s1[NBPLANE];
__device__ __align__(16) __nv_bfloat16 g_th[20L * NBPLANE];  // dw outputs, hi plane
__device__ __align__(16) __nv_bfloat16 g_tl[20L * NBPLANE];  // dw outputs, lo plane
__device__ __align__(16) float g_u[10L * NBPLANE];           // sep pw1 outputs (fp32)
__device__ __align__(16) __nv_bfloat16 g_wh[6L * WSZ];       // pre-split weights hi
__device__ __align__(16) __nv_bfloat16 g_wl[6L * WSZ];       // pre-split weights lo
__device__ __align__(16) float g_pw[NMIX * NB * 8];

// ---------------- bf16 split helpers ----------------
__device__ __forceinline__ uint32_t packbf2(float e0, float e1) {
    uint32_t r;
    asm("cvt.rn.bf16x2.f32 %0, %1, %2;" : "=r"(r) : "f"(e1), "f"(e0));
    return r;
}
__device__ __forceinline__ void split4(float4 v, uint32_t& h0, uint32_t& h1,
                                       uint32_t& l0, uint32_t& l1) {
    h0 = packbf2(v.x, v.y);
    h1 = packbf2(v.z, v.w);
    float rx = v.x - __uint_as_float(h0 << 16);
    float ry = v.y - __uint_as_float(h0 & 0xffff0000u);
    float rz = v.z - __uint_as_float(h1 << 16);
    float rw = v.w - __uint_as_float(h1 & 0xffff0000u);
    l0 = packbf2(rx, ry);
    l1 = packbf2(rz, rw);
}
__device__ __forceinline__ void relu4(float4& v) {
    v.x = fmaxf(v.x, 0.f); v.y = fmaxf(v.y, 0.f);
    v.z = fmaxf(v.z, 0.f); v.w = fmaxf(v.w, 0.f);
}

// ---------------- gate kernel: top-2 + masked softmax ----------------
__global__ void gate_kernel(const float* __restrict__ gates, float* __restrict__ P) {
    int idx = blockIdx.x * blockDim.x + threadIdx.x;
    if (idx >= NMIX * NB) return;
    const float* g = gates + idx * 8;
    float gv[8];
#pragma unroll
    for (int j = 0; j < 8; j++) gv[j] = g[j];
    bool sel[8] = {false, false, false, false, false, false, false, false};
    for (int t = 0; t < 2; t++) {
        int best = -1; float bv = -3.4e38f;
#pragma unroll
        for (int j = 0; j < 8; j++)
            if (!sel[j] && gv[j] > bv) { bv = gv[j]; best = j; }
        sel[best] = true;
    }
    float mx = -3.4e38f;
#pragma unroll
    for (int j = 0; j < 8; j++) if (sel[j]) mx = fmaxf(mx, gv[j]);
    float e[8]; float s = 0.f;
#pragma unroll
    for (int j = 0; j < 8; j++) { e[j] = sel[j] ? expf(gv[j] - mx) : 0.f; s += e[j]; }
#pragma unroll
    for (int j = 0; j < 8; j++) P[idx * 8 + j] = e[j] / s;
}

// ---------------- weight pre-split kernel ----------------
struct WprepArgs { const float* W[6]; };
__global__ void wprep_kernel(WprepArgs wa, __nv_bfloat16* wh, __nv_bfloat16* wl) {
    long idx = (long)blockIdx.x * blockDim.x + threadIdx.x;
    if (idx >= 6L * WSZ) return;
    int set = (int)(idx / WSZ);
    long rem = idx - (long)set * WSZ;
    float v = wa.W[set][rem];
    __nv_bfloat16 h = __float2bfloat16(v);
    wh[idx] = h;
    wl[idx] = __float2bfloat16(v - __bfloat162float(h));
}

// ---------------- fused pool/skip kernel ----------------
struct PoolArgs {
    const float* X[5]; long bsX[5];
    const float* P[5];
    float* O; long bsO;
    int nj;
};

__global__ __launch_bounds__(256) void pool_kernel(PoolArgs pa) {
    int c = blockIdx.x, b = blockIdx.y, tid = threadIdx.x;
    __shared__ float st[1024];
    int py = tid >> 3, px0 = (tid & 7) * 4;
    float acc0 = 0.f, acc1 = 0.f, acc2 = 0.f, acc3 = 0.f;
    for (int j = 0; j < pa.nj; j++) {
        const float* pj = pa.P[j] + b * 8;
        float p1 = pj[1], p2 = pj[2], p3 = pj[3];
        if (p1 == 0.f && p2 == 0.f && p3 == 0.f) continue;   // uniform over block
        __syncthreads();
        const float* xp = pa.X[j] + (long)b * pa.bsX[j] + c * HW;
        for (int i = tid; i < 1024; i += 256) st[i] = xp[i];
        __syncthreads();
        float mx0 = -3.4e38f, mx1 = -3.4e38f, mx2 = -3.4e38f, mx3 = -3.4e38f;
        float s0 = 0.f, s1 = 0.f, s2 = 0.f, s3 = 0.f;
        int rows = 0;
#pragma unroll
        for (int dy = -1; dy <= 1; dy++) {
            int yy = py + dy;
            if (yy < 0 || yy > 31) continue;
            rows++;
            const float* rp = st + yy * 32 + px0;
            float v0 = (px0 > 0)  ? rp[-1] : 0.f;
            float m0 = (px0 > 0)  ? v0 : -3.4e38f;
            float v1 = rp[0], v2 = rp[1], v3 = rp[2], v4 = rp[3];
            float v5 = (px0 < 28) ? rp[4] : 0.f;
            float m5 = (px0 < 28) ? v5 : -3.4e38f;
            s0 += v0 + v1 + v2;  s1 += v1 + v2 + v3;
            s2 += v2 + v3 + v4;  s3 += v3 + v4 + v5;
            mx0 = fmaxf(mx0, fmaxf(m0, fmaxf(v1, v2)));
            mx1 = fmaxf(mx1, fmaxf(v1, fmaxf(v2, v3)));
            mx2 = fmaxf(mx2, fmaxf(v2, fmaxf(v3, v4)));
            mx3 = fmaxf(mx3, fmaxf(v3, fmaxf(v4, m5)));
        }
        float c0 = (float)(rows * (3 - (px0 == 0)));
        float c12 = (float)(rows * 3);
        float c3 = (float)(rows * (3 - (px0 == 28)));
        const float* ctr = st + py * 32 + px0;
        acc0 += p1 * (BNS * mx0) + p2 * (BNS * (s0 / c0))  + p3 * ctr[0];
        acc1 += p1 * (BNS * mx1) + p2 * (BNS * (s1 / c12)) + p3 * ctr[1];
        acc2 += p1 * (BNS * mx2) + p2 * (BNS * (s2 / c12)) + p3 * ctr[2];
        acc3 += p1 * (BNS * mx3) + p2 * (BNS * (s3 / c3))  + p3 * ctr[3];
    }
    float* op = pa.O + (long)b * pa.bsO + c * HW + py * 32 + px0;
    *(float4*)op = make_float4(acc0, acc1, acc2, acc3);   // sole writer pre-GEMM
}

// ---------------- fused multi-entry depthwise conv (bf16 hi/lo output) ----------------
struct DwArgs {
    const float* X[20]; long bsX[20];
    const float* W[20];
    __nv_bfloat16* Yh[20];
    __nv_bfloat16* Yl[20];
    const float* P[20];
    int ks[20], dil[20];
};

template<int KS, int DIL, int PAD>
__device__ __forceinline__ float4 dw_inner4(const float* __restrict__ st,
                                            const float* __restrict__ w,
                                            int py, int px0)
{
    const float* base = st + (py + 4 - PAD) * 40 + (px0 + 4 - PAD);
    float a0 = 0.f, a1 = 0.f, a2 = 0.f, a3 = 0.f;
#pragma unroll
    for (int i = 0; i < KS; i++) {
        const float* rp = base + i * DIL * 40;
        float r[(KS - 1) * DIL + 4];
#pragma unroll
        for (int cidx = 0; cidx < (KS - 1) * DIL + 4; cidx++) r[cidx] = rp[cidx];
#pragma unroll
        for (int j = 0; j < KS; j++) {
            float wv = w[i * KS + j];
            a0 += wv * r[j * DIL + 0];
            a1 += wv * r[j * DIL + 1];
            a2 += wv * r[j * DIL + 2];
            a3 += wv * r[j * DIL + 3];
        }
    }
    return make_float4(a0, a1, a2, a3);
}

__global__ __launch_bounds__(256) void dw_kernel(DwArgs da) {
    int e = blockIdx.z, b = blockIdx.y, c = blockIdx.x;
    if (da.P[e][b * 8] == 0.f) return;
    __shared__ float st[1600];  // 40x40, relu(x) with zero halo (max pad 4)
    int tid = threadIdx.x;
    for (int i = tid; i < 1600; i += 256) st[i] = 0.f;
    __syncthreads();
    const float* xp = da.X[e] + (long)b * da.bsX[e] + c * HW;
    for (int i = tid; i < 1024; i += 256) {
        int y = i >> 5, x = i & 31;
        st[(y + 4) * 40 + x + 4] = fmaxf(xp[i], 0.f);
    }
    __syncthreads();
    int ks = da.ks[e];
    int ksz = ks * ks;
    const float* wp = da.W[e] + c * ksz;
    float w[25];
#pragma unroll
    for (int i = 0; i < 25; i++) w[i] = (i < ksz) ? wp[i] : 0.f;
    int py = tid >> 3, px0 = (tid & 7) * 4;
    float4 acc;
    int dil = da.dil[e];
    if (ks == 3 && dil == 1)      acc = dw_inner4<3,1,1>(st, w, py, px0);
    else if (ks == 5 && dil == 1) acc = dw_inner4<5,1,2>(st, w, py, px0);
    else if (ks == 3)             acc = dw_inner4<3,2,2>(st, w, py, px0);
    else                          acc = dw_inner4<5,2,4>(st, w, py, px0);
    uint32_t h0, h1, l0, l1;
    split4(acc, h0, h1, l0, l1);
    long oidx = (long)b * PLANE + c * HW + py * 32 + px0;
    *(uint2*)(da.Yh[e] + oidx) = make_uint2(h0, h1);
    *(uint2*)(da.Yl[e] + oidx) = make_uint2(l0, l1);
}

// ---------------- tensor-core GEMM helpers ----------------
__device__ __forceinline__ void ldsm4(uint32_t* d, uint32_t addr) {
    asm volatile("ldmatrix.sync.aligned.m8n8.x4.shared.b16 {%0,%1,%2,%3}, [%4];"
                 : "=r"(d[0]), "=r"(d[1]), "=r"(d[2]), "=r"(d[3]) : "r"(addr));
}
__device__ __forceinline__ void ldsm4t(uint32_t* d, uint32_t addr) {
    asm volatile("ldmatrix.sync.aligned.m8n8.x4.trans.shared.b16 {%0,%1,%2,%3}, [%4];"
                 : "=r"(d[0]), "=r"(d[1]), "=r"(d[2]), "=r"(d[3]) : "r"(addr));
}
__device__ __forceinline__ void mma16816(float* c, const uint32_t* a,
                                         uint32_t b0, uint32_t b1) {
    asm volatile("mma.sync.aligned.m16n8k16.row.col.f32.bf16.bf16.f32 "
                 "{%0,%1,%2,%3}, {%4,%5,%6,%7}, {%8,%9}, {%0,%1,%2,%3};"
                 : "+f"(c[0]), "+f"(c[1]), "+f"(c[2]), "+f"(c[3])
                 : "r"(a[0]), "r"(a[1]), "r"(a[2]), "r"(a[3]), "r"(b0), "r"(b1));
}

#define A_LD 24    // halfs per A smem row
#define B_LD 136   // halfs per B smem row

// ---------------- GEMM on pre-split bf16 planes (mixed-op pointwise convs) ----------------
struct GemmPsArgs {
    const __nv_bfloat16* Ah[20];
    const __nv_bfloat16* Al[20];
    const __nv_bfloat16* Bh[20];
    const __nv_bfloat16* Bl[20];
    float*       Cp[20];
    const float* P[20];
    int          byP[20];
    int          accum[20];
    long         bsC[20];
};

__global__ __launch_bounds__(256) void gemm_ps(GemmPsArgs ga) {
    int e = blockIdx.z, b = blockIdx.y;
    float pv = ga.P[e][b * 8];
    if (pv == 0.f) return;
    float scale = BNS * (ga.byP[e] ? pv : 1.f);

    __shared__ __align__(16) __nv_bfloat16 As[2][128][A_LD];
    __shared__ __align__(16) __nv_bfloat16 Bs[2][16][B_LD];

    int tid  = threadIdx.x;
    int lane = tid & 31, w = tid >> 5;
    int wm = (w & 3) * 32;
    int wn = (w >> 2) * 64;

    int am = tid >> 1, ak = (tid & 1) * 8;
    int bk = tid >> 4, bc = (tid & 15) * 8;

    const __nv_bfloat16* Ahp = ga.Ah[e] + am * CC + ak;
    const __nv_bfloat16* Alp = ga.Al[e] + am * CC + ak;
    const __nv_bfloat16* Bhp = ga.Bh[e] + (long)b * PLANE + blockIdx.x * 128
                               + (long)bk * HW + bc;
    const __nv_bfloat16* Blp = ga.Bl[e] + (long)b * PLANE + blockIdx.x * 128
                               + (long)bk * HW + bc;
    float* Cm = ga.Cp[e] + (long)b * ga.bsC[e] + blockIdx.x * 128;

    int r8 = lane & 7, quad = lane >> 3;
    int lrow = r8 + (quad & 1) * 8;
    int lcol = (quad >> 1) * 8;

    uint32_t asBase = (uint32_t)__cvta_generic_to_shared(&As[0][0][0]);
    uint32_t bsBase = (uint32_t)__cvta_generic_to_shared(&Bs[0][0][0]);
    uint32_t aAddr[2][2], bAddr[2][4];
#pragma unroll
    for (int p = 0; p < 2; p++) {
#pragma unroll
        for (int mt = 0; mt < 2; mt++)
            aAddr[p][mt] = asBase + ((p * 128 + wm + mt * 16 + lrow) * A_LD + lcol) * 2;
#pragma unroll
        for (int i = 0; i < 4; i++)
            bAddr[p][i] = bsBase + ((p * 16 + lrow) * B_LD + wn + i * 16 + lcol) * 2;
    }

    float acc[2][8][4];
#pragma unroll
    for (int mt = 0; mt < 2; mt++)
#pragma unroll
        for (int nt = 0; nt < 8; nt++)
#pragma unroll
            for (int q = 0; q < 4; q++) acc[mt][nt][q] = 0.f;

    uint4 rah = *(const uint4*)(Ahp);
    uint4 ral = *(const uint4*)(Alp);
    uint4 rbh = *(const uint4*)(Bhp);
    uint4 rbl = *(const uint4*)(Blp);

    const int T = CC >> 4;   // 8
    for (int t = 0; t < T; t++) {
        *(uint4*)&As[0][am][ak] = rah;
        *(uint4*)&As[1][am][ak] = ral;
        *(uint4*)&Bs[0][bk][bc] = rbh;
        *(uint4*)&Bs[1][bk][bc] = rbl;
        __syncthreads();

        bool more = (t + 1 < T);
        if (more) {
            rah = *(const uint4*)(Ahp + (t + 1) * 16);
            ral = *(const uint4*)(Alp + (t + 1) * 16);
            rbh = *(const uint4*)(Bhp + (long)(t + 1) * 16 * HW);
            rbl = *(const uint4*)(Blp + (long)(t + 1) * 16 * HW);
        }

        uint32_t afr[2][2][4];
        uint32_t bfr[2][4][4];
#pragma unroll
        for (int p = 0; p < 2; p++) {
#pragma unroll
            for (int mt = 0; mt < 2; mt++) ldsm4(afr[p][mt], aAddr[p][mt]);
#pragma unroll
            for (int i = 0; i < 4; i++)    ldsm4t(bfr[p][i], bAddr[p][i]);
        }
#pragma unroll
        for (int combo = 0; combo < 3; combo++) {
            int ap = (combo == 1) ? 1 : 0;
            int bp = (combo == 2) ? 1 : 0;
#pragma unroll
            for (int mt = 0; mt < 2; mt++)
#pragma unroll
                for (int nt = 0; nt < 8; nt++) {
                    int i = nt >> 1, po = (nt & 1) * 2;
                    mma16816(acc[mt][nt], afr[ap][mt], bfr[bp][i][po], bfr[bp][i][po + 1]);
                }
        }
        __syncthreads();
    }

    int g = lane >> 2, tig = lane & 3;
    if (ga.accum[e]) {
#pragma unroll
        for (int mt = 0; mt < 2; mt++)
#pragma unroll
            for (int nt = 0; nt < 8; nt++) {
                int row = wm + mt * 16 + g;
                int col = wn + nt * 8 + tig * 2;
                float* p0 = Cm + (long)row * HW + col;
                float* p1 = p0 + 8 * HW;
                atomicAdd(&p0[0], scale * acc[mt][nt][0]);
                atomicAdd(&p0[1], scale * acc[mt][nt][1]);
                atomicAdd(&p1[0], scale * acc[mt][nt][2]);
                atomicAdd(&p1[1], scale * acc[mt][nt][3]);
            }
    } else {
#pragma unroll
        for (int mt = 0; mt < 2; mt++)
#pragma unroll
            for (int nt = 0; nt < 8; nt++) {
                int row = wm + mt * 16 + g;
                int col = wn + nt * 8 + tig * 2;
                float* p0 = Cm + (long)row * HW + col;
                float* p1 = p0 + 8 * HW;
                *(float2*)p0 = make_float2(scale * acc[mt][nt][0], scale * acc[mt][nt][1]);
                *(float2*)p1 = make_float2(scale * acc[mt][nt][2], scale * acc[mt][nt][3]);
            }
    }
}

// ---------------- preprocess GEMM (fp32 src, on-the-fly split, relu, K=512) ----------------
struct PreArgs { const float* A[2]; const float* B[2]; float* Cp[2]; };

__global__ __launch_bounds__(256) void gemm_pre(PreArgs pa) {
    int e = blockIdx.z, b = blockIdx.y;

    __shared__ __align__(16) __nv_bfloat16 As[2][128][A_LD];
    __shared__ __align__(16) __nv_bfloat16 Bs[2][16][B_LD];

    int tid  = threadIdx.x;
    int lane = tid & 31, w = tid >> 5;
    int wm = (w & 3) * 32;
    int wn = (w >> 2) * 64;

    int am = tid >> 1, ak = (tid & 1) * 8;
    int bk = tid >> 4, bc = (tid & 15) * 8;

    const float* Aptr = pa.A[e] + (long)am * CIN + ak;
    const float* Bptr = pa.B[e] + (long)b * CIN * HW + blockIdx.x * 128
                        + (long)bk * HW + bc;
    float* Cm = pa.Cp[e] + (long)b * PLANE + blockIdx.x * 128;

    int r8 = lane & 7, quad = lane >> 3;
    int lrow = r8 + (quad & 1) * 8;
    int lcol = (quad >> 1) * 8;

    uint32_t asBase = (uint32_t)__cvta_generic_to_shared(&As[0][0][0]);
    uint32_t bsBase = (uint32_t)__cvta_generic_to_shared(&Bs[0][0][0]);
    uint32_t aAddr[2][2], bAddr[2][4];
#pragma unroll
    for (int p = 0; p < 2; p++) {
#pragma unroll
        for (int mt = 0; mt < 2; mt++)
            aAddr[p][mt] = asBase + ((p * 128 + wm + mt * 16 + lrow) * A_LD + lcol) * 2;
#pragma unroll
        for (int i = 0; i < 4; i++)
            bAddr[p][i] = bsBase + ((p * 16 + lrow) * B_LD + wn + i * 16 + lcol) * 2;
    }

    float acc[2][8][4];
#pragma unroll
    for (int mt = 0; mt < 2; mt++)
#pragma unroll
        for (int nt = 0; nt < 8; nt++)
#pragma unroll
            for (int q = 0; q < 4; q++) acc[mt][nt][q] = 0.f;

    float4 ra0 = *(const float4*)(Aptr);
    float4 ra1 = *(const float4*)(Aptr + 4);
    float4 rb0 = *(const float4*)(Bptr);
    float4 rb1 = *(const float4*)(Bptr + 4);

    const int T = CIN >> 4;   // 32
    for (int t = 0; t < T; t++) {
        relu4(rb0); relu4(rb1);
        {
            uint32_t h0, h1, h2, h3, l0, l1, l2, l3;
            split4(ra0, h0, h1, l0, l1);
            split4(ra1, h2, h3, l2, l3);
            *(uint4*)&As[0][am][ak] = make_uint4(h0, h1, h2, h3);
            *(uint4*)&As[1][am][ak] = make_uint4(l0, l1, l2, l3);
        }
        {
            uint32_t h0, h1, h2, h3, l0, l1, l2, l3;
            split4(rb0, h0, h1, l0, l1);
            split4(rb1, h2, h3, l2, l3);
            *(uint4*)&Bs[0][bk][bc] = make_uint4(h0, h1, h2, h3);
            *(uint4*)&Bs[1][bk][bc] = make_uint4(l0, l1, l2, l3);
        }
        __syncthreads();

        bool more = (t + 1 < T);
        if (more) {
            ra0 = *(const float4*)(Aptr + (t + 1) * 16);
            ra1 = *(const float4*)(Aptr + (t + 1) * 16 + 4);
            const float* bp = Bptr + (long)(t + 1) * 16 * HW;
            rb0 = *(const float4*)(bp);
            rb1 = *(const float4*)(bp + 4);
        }

        uint32_t afr[2][2][4];
        uint32_t bfr[2][4][4];
#pragma unroll
        for (int p = 0; p < 2; p++) {
#pragma unroll
            for (int mt = 0; mt < 2; mt++) ldsm4(afr[p][mt], aAddr[p][mt]);
#pragma unroll
            for (int i = 0; i < 4; i++)    ldsm4t(bfr[p][i], bAddr[p][i]);
        }
#pragma unroll
        for (int combo = 0; combo < 3; combo++) {
            int ap = (combo == 1) ? 1 : 0;
            int bp = (combo == 2) ? 1 : 0;
#pragma unroll
            for (int mt = 0; mt < 2; mt++)
#pragma unroll
                for (int nt = 0; nt < 8; nt++) {
                    int i = nt >> 1, po = (nt & 1) * 2;
                    mma16816(acc[mt][nt], afr[ap][mt], bfr[bp][i][po], bfr[bp][i][po + 1]);
                }
        }
        __syncthreads();
    }

    int g = lane >> 2, tig = lane & 3;
#pragma unroll
    for (int mt = 0; mt < 2; mt++)
#pragma unroll
        for (int nt = 0; nt < 8; nt++) {
            int row = wm + mt * 16 + g;
            int col = wn + nt * 8 + tig * 2;
            float* p0 = Cm + (long)row * HW + col;
            float* p1 = p0 + 8 * HW;
            *(float2*)p0 = make_float2(BNS * acc[mt][nt][0], BNS * acc[mt][nt][1]);
            *(float2*)p1 = make_float2(BNS * acc[mt][nt][2], BNS * acc[mt][nt][3]);
        }
}

// ---------------- host orchestration ----------------
extern "C" void kernel_launch(void* const* d_in, const int* in_sizes, int n_in,
                              void* d_out, int out_size) {
    const float* s0r   = (const float*)d_in[0];
    const float* s1r   = (const float*)d_in[1];
    const float* gates = (const float*)d_in[2];
    const float* pre0  = (const float*)d_in[3];
    const float* pre1  = (const float*)d_in[4];
    const float* s3d1  = (const float*)d_in[5];
    const float* s3p1  = (const float*)d_in[6];
    const float* s3d2  = (const float*)d_in[7];
    const float* s3p2  = (const float*)d_in[8];
    const float* s5d1  = (const float*)d_in[9];
    const float* s5p1  = (const float*)d_in[10];
    const float* s5d2  = (const float*)d_in[11];
    const float* s5p2  = (const float*)d_in[12];
    const float* d3d   = (const float*)d_in[13];
    const float* d3p   = (const float*)d_in[14];
    const float* d5d   = (const float*)d_in[15];
    const float* d5p   = (const float*)d_in[16];
    float* out = (float*)d_out;

    float *ps0, *ps1, *pu, *pp;
    __nv_bfloat16 *pth, *ptl, *pwh, *pwl;
    cudaGetSymbolAddress((void**)&ps0, g_s0);
    cudaGetSymbolAddress((void**)&ps1, g_s1);
    cudaGetSymbolAddress((void**)&pth, g_th);
    cudaGetSymbolAddress((void**)&ptl, g_tl);
    cudaGetSymbolAddress((void**)&pu,  g_u);
    cudaGetSymbolAddress((void**)&pwh, g_wh);
    cudaGetSymbolAddress((void**)&pwl, g_wl);
    cudaGetSymbolAddress((void**)&pp,  g_pw);

    gate_kernel<<<2, 256>>>(gates, pp);

    // pre-split the 6 pointwise weight sets into bf16 hi/lo
    {
        WprepArgs wa = {};
        wa.W[0] = s3p1; wa.W[1] = s5p1; wa.W[2] = d3p;
        wa.W[3] = d5p;  wa.W[4] = s3p2; wa.W[5] = s5p2;
        int total = 6 * WSZ;
        wprep_kernel<<<(total + 255) / 256, 256>>>(wa, pwh, pwl);
    }

    // preprocess: s0/s1 -> states 0/1
    {
        PreArgs pa = {};
        pa.A[0] = pre0; pa.B[0] = s0r; pa.Cp[0] = ps0;
        pa.A[1] = pre1; pa.B[1] = s1r; pa.Cp[1] = ps1;
        gemm_pre<<<dim3(8, NB, 2), 256>>>(pa);
    }

    struct StateDesc { float* p; long bs; };
    StateDesc st[6] = {
        {ps0, (long)PLANE}, {ps1, (long)PLANE},
        {out,             512L * HW}, {out + PLANE,     512L * HW},
        {out + 2 * PLANE, 512L * HW}, {out + 3 * PLANE, 512L * HW}
    };

    const float* dw1w[4]  = {s3d1, s5d1, d3d, d5d};
    const long   dw1sz[4] = {9, 25, 9, 25};
    const int    dwk[4]   = {3, 5, 3, 5};
    const int    dwdil[4] = {1, 1, 2, 2};

    int offset = 0;
    for (int i = 0; i < 4; i++) {
        int nj = 2 + i;
        StateDesc dst = st[2 + i];

        // pools + skip
        PoolArgs pa = {};
        for (int j = 0; j < nj; j++) {
            pa.X[j] = st[j].p; pa.bsX[j] = st[j].bs;
            pa.P[j] = pp + (long)(offset + j) * NB * 8;
        }
        pa.O = dst.p; pa.bsO = dst.bs; pa.nj = nj;
        pool_kernel<<<dim3(CC, NB), 256>>>(pa);

        // dw1
        DwArgs d1 = {};
        for (int j = 0; j < nj; j++) {
            int m = offset + j;
            const float* gp = pp + (long)m * NB * 8;
            for (int br = 0; br < 4; br++) {
                int e = j * 4 + br;
                d1.X[e] = st[j].p; d1.bsX[e] = st[j].bs;
                d1.W[e] = dw1w[br] + (long)m * CC * dw1sz[br];
                d1.Yh[e] = pth + (long)e * NBPLANE;
                d1.Yl[e] = ptl + (long)e * NBPLANE;
                d1.P[e] = gp + 4 + br;
                d1.ks[e] = dwk[br]; d1.dil[e] = dwdil[br];
            }
        }
        dw_kernel<<<dim3(CC, NB, nj * 4), 256>>>(d1);

        // gemm1: sep pw1 -> u (store), dil pw -> dst (scaled atomic accumulate)
        GemmPsArgs g1 = {};
        for (int j = 0; j < nj; j++) {
            int m = offset + j;
            const float* gp = pp + (long)m * NB * 8;
            for (int br = 0; br < 4; br++) {
                int e = j * 4 + br;
                g1.Ah[e] = pwh + (long)br * WSZ + (long)m * CC * CC;
                g1.Al[e] = pwl + (long)br * WSZ + (long)m * CC * CC;
                g1.Bh[e] = pth + (long)e * NBPLANE;
                g1.Bl[e] = ptl + (long)e * NBPLANE;
                g1.P[e] = gp + 4 + br;
                if (br < 2) {
                    g1.Cp[e] = pu + (long)(j * 2 + br) * NBPLANE;
                    g1.byP[e] = 0; g1.accum[e] = 0; g1.bsC[e] = PLANE;
                } else {
                    g1.Cp[e] = dst.p;
                    g1.byP[e] = 1; g1.accum[e] = 1; g1.bsC[e] = dst.bs;
                }
            }
        }
        gemm_ps<<<dim3(8, NB, nj * 4), 256>>>(g1);

        // dw2: sep3_dw2 / sep5_dw2 on relu(u)
        DwArgs d2 = {};
        for (int j = 0; j < nj; j++) {
            int m = offset + j;
            const float* gp = pp + (long)m * NB * 8;
            for (int br = 0; br < 2; br++) {
                int e = j * 2 + br;
                d2.X[e] = pu + (long)e * NBPLANE; d2.bsX[e] = PLANE;
                d2.W[e] = (br == 0 ? s3d2 + (long)m * CC * 9 : s5d2 + (long)m * CC * 25);
                d2.Yh[e] = pth + (long)(j * 4 + br) * NBPLANE;
                d2.Yl[e] = ptl + (long)(j * 4 + br) * NBPLANE;
                d2.P[e] = gp + 4 + br;
                d2.ks[e] = (br == 0 ? 3 : 5); d2.dil[e] = 1;
            }
        }
        dw_kernel<<<dim3(CC, NB, nj * 2), 256>>>(d2);

        // gemm2: sep pw2 -> dst (scaled atomic accumulate)
        GemmPsArgs g2 = {};
        for (int j = 0; j < nj; j++) {
            int m = offset + j;
            const float* gp = pp + (long)m * NB * 8;
            for (int br = 0; br < 2; br++) {
                int e = j * 2 + br;
                int set = 4 + br;
                g2.Ah[e] = pwh + (long)set * WSZ + (long)m * CC * CC;
                g2.Al[e] = pwl + (long)set * WSZ + (long)m * CC * CC;
                g2.Bh[e] = pth + (long)(j * 4 + br) * NBPLANE;
                g2.Bl[e] = ptl + (long)(j * 4 + br) * NBPLANE;
                g2.Cp[e] = dst.p;
                g2.P[e] = gp + 4 + br;
                g2.byP[e] = 1; g2.accum[e] = 1; g2.bsC[e] = dst.bs;
            }
        }
        gemm_ps<<<dim3(8, NB, nj * 2), 256>>>(g2);

        offset += nj;
    }
}

// round 12
// speedup vs baseline: 1.2017x; 1.2017x over previous
#include <cuda_runtime.h>
#include <cuda_bf16.h>
#include <cstdint>

// ---------------- problem constants ----------------
#define NB    32          // batch
#define CC    128         // cell channels
#define CIN   512         // input channels
#define HW    1024        // 32*32
#define PLANE (CC*HW)     // 131072 per (batch, state)
#define NBPLANE (NB*PLANE)
#define NMIX  14
#define BNS   0.9999950000374997f   // 1/sqrt(1+1e-5)

// ---------------- device scratch (static, allocation-free) ----------------
__device__ __align__(16) float g_s0[NBPLANE];
__device__ __align__(16) float g_s1[NBPLANE];
__device__ __align__(16) float g_t[20L * NBPLANE];   // dw outputs (fp32)
__device__ __align__(16) float g_u[10L * NBPLANE];   // sep pw1 outputs (fp32)
__device__ __align__(16) float g_pw[NMIX * NB * 8];

// ---------------- bf16 split helpers ----------------
__device__ __forceinline__ uint32_t packbf2(float e0, float e1) {
    uint32_t r;
    asm("cvt.rn.bf16x2.f32 %0, %1, %2;" : "=r"(r) : "f"(e1), "f"(e0));
    return r;
}
__device__ __forceinline__ void split4(float4 v, uint32_t& h0, uint32_t& h1,
                                       uint32_t& l0, uint32_t& l1) {
    h0 = packbf2(v.x, v.y);
    h1 = packbf2(v.z, v.w);
    float rx = v.x - __uint_as_float(h0 << 16);
    float ry = v.y - __uint_as_float(h0 & 0xffff0000u);
    float rz = v.z - __uint_as_float(h1 << 16);
    float rw = v.w - __uint_as_float(h1 & 0xffff0000u);
    l0 = packbf2(rx, ry);
    l1 = packbf2(rz, rw);
}
__device__ __forceinline__ void relu4(float4& v) {
    v.x = fmaxf(v.x, 0.f); v.y = fmaxf(v.y, 0.f);
    v.z = fmaxf(v.z, 0.f); v.w = fmaxf(v.w, 0.f);
}

// ---------------- gate kernel: top-2 + masked softmax ----------------
__global__ void gate_kernel(const float* __restrict__ gates, float* __restrict__ P) {
    int idx = blockIdx.x * blockDim.x + threadIdx.x;
    if (idx >= NMIX * NB) return;
    const float* g = gates + idx * 8;
    float gv[8];
#pragma unroll
    for (int j = 0; j < 8; j++) gv[j] = g[j];
    bool sel[8] = {false, false, false, false, false, false, false, false};
    for (int t = 0; t < 2; t++) {      // top = 2 fixed by setup_inputs
        int best = -1; float bv = -3.4e38f;
#pragma unroll
        for (int j = 0; j < 8; j++)
            if (!sel[j] && gv[j] > bv) { bv = gv[j]; best = j; }
        sel[best] = true;
    }
    float mx = -3.4e38f;
#pragma unroll
    for (int j = 0; j < 8; j++) if (sel[j]) mx = fmaxf(mx, gv[j]);
    float e[8]; float s = 0.f;
#pragma unroll
    for (int j = 0; j < 8; j++) { e[j] = sel[j] ? expf(gv[j] - mx) : 0.f; s += e[j]; }
#pragma unroll
    for (int j = 0; j < 8; j++) P[idx * 8 + j] = e[j] / s;
}

// ---------------- fused pool/skip kernel (4 consecutive px per thread) ----------------
struct PoolArgs {
    const float* X[5]; long bsX[5];
    const float* P[5];
    float* O; long bsO;
    int nj;
};

__global__ __launch_bounds__(256) void pool_kernel(PoolArgs pa) {
    int c = blockIdx.x, b = blockIdx.y, tid = threadIdx.x;
    __shared__ float st[1024];
    int py = tid >> 3, px0 = (tid & 7) * 4;
    float acc0 = 0.f, acc1 = 0.f, acc2 = 0.f, acc3 = 0.f;
    for (int j = 0; j < pa.nj; j++) {
        const float* pj = pa.P[j] + b * 8;
        float p1 = pj[1], p2 = pj[2], p3 = pj[3];
        if (p1 == 0.f && p2 == 0.f && p3 == 0.f) continue;   // uniform over block
        __syncthreads();
        const float* xp = pa.X[j] + (long)b * pa.bsX[j] + c * HW;
        for (int i = tid; i < 1024; i += 256) st[i] = xp[i];
        __syncthreads();
        float mx0 = -3.4e38f, mx1 = -3.4e38f, mx2 = -3.4e38f, mx3 = -3.4e38f;
        float s0 = 0.f, s1 = 0.f, s2 = 0.f, s3 = 0.f;
        int rows = 0;
#pragma unroll
        for (int dy = -1; dy <= 1; dy++) {
            int yy = py + dy;
            if (yy < 0 || yy > 31) continue;
            rows++;
            const float* rp = st + yy * 32 + px0;
            float v0 = (px0 > 0)  ? rp[-1] : 0.f;
            float m0 = (px0 > 0)  ? v0 : -3.4e38f;
            float v1 = rp[0], v2 = rp[1], v3 = rp[2], v4 = rp[3];
            float v5 = (px0 < 28) ? rp[4] : 0.f;
            float m5 = (px0 < 28) ? v5 : -3.4e38f;
            s0 += v0 + v1 + v2;  s1 += v1 + v2 + v3;
            s2 += v2 + v3 + v4;  s3 += v3 + v4 + v5;
            mx0 = fmaxf(mx0, fmaxf(m0, fmaxf(v1, v2)));
            mx1 = fmaxf(mx1, fmaxf(v1, fmaxf(v2, v3)));
            mx2 = fmaxf(mx2, fmaxf(v2, fmaxf(v3, v4)));
            mx3 = fmaxf(mx3, fmaxf(v3, fmaxf(v4, m5)));
        }
        float c0 = (float)(rows * (3 - (px0 == 0)));
        float c12 = (float)(rows * 3);
        float c3 = (float)(rows * (3 - (px0 == 28)));
        const float* ctr = st + py * 32 + px0;
        acc0 += p1 * (BNS * mx0) + p2 * (BNS * (s0 / c0))  + p3 * ctr[0];
        acc1 += p1 * (BNS * mx1) + p2 * (BNS * (s1 / c12)) + p3 * ctr[1];
        acc2 += p1 * (BNS * mx2) + p2 * (BNS * (s2 / c12)) + p3 * ctr[2];
        acc3 += p1 * (BNS * mx3) + p2 * (BNS * (s3 / c3))  + p3 * ctr[3];
    }
    float* op = pa.O + (long)b * pa.bsO + c * HW + py * 32 + px0;
    *(float4*)op = make_float4(acc0, acc1, acc2, acc3);   // sole writer pre-GEMM
}

// ---------------- fused multi-entry depthwise conv (4 consecutive px, fp32 out) ----------------
struct DwArgs {
    const float* X[20]; long bsX[20];
    const float* W[20];
    float*       Y[20];
    const float* P[20];
    int ks[20], dil[20];
};

template<int KS, int DIL, int PAD>
__device__ __forceinline__ float4 dw_inner4(const float* __restrict__ st,
                                            const float* __restrict__ w,
                                            int py, int px0)
{
    const float* base = st + (py + 4 - PAD) * 40 + (px0 + 4 - PAD);
    float a0 = 0.f, a1 = 0.f, a2 = 0.f, a3 = 0.f;
#pragma unroll
    for (int i = 0; i < KS; i++) {
        const float* rp = base + i * DIL * 40;
        float r[(KS - 1) * DIL + 4];
#pragma unroll
        for (int cidx = 0; cidx < (KS - 1) * DIL + 4; cidx++) r[cidx] = rp[cidx];
#pragma unroll
        for (int j = 0; j < KS; j++) {
            float wv = w[i * KS + j];
            a0 += wv * r[j * DIL + 0];
            a1 += wv * r[j * DIL + 1];
            a2 += wv * r[j * DIL + 2];
            a3 += wv * r[j * DIL + 3];
        }
    }
    return make_float4(a0, a1, a2, a3);
}

__global__ __launch_bounds__(256) void dw_kernel(DwArgs da) {
    int e = blockIdx.z, b = blockIdx.y, c = blockIdx.x;
    if (da.P[e][b * 8] == 0.f) return;
    __shared__ float st[1600];  // 40x40, relu(x) with zero halo (max pad 4)
    int tid = threadIdx.x;
    for (int i = tid; i < 1600; i += 256) st[i] = 0.f;
    __syncthreads();
    const float* xp = da.X[e] + (long)b * da.bsX[e] + c * HW;
    for (int i = tid; i < 1024; i += 256) {
        int y = i >> 5, x = i & 31;
        st[(y + 4) * 40 + x + 4] = fmaxf(xp[i], 0.f);
    }
    __syncthreads();
    int ks = da.ks[e];
    int ksz = ks * ks;
    const float* wp = da.W[e] + c * ksz;
    float w[25];
#pragma unroll
    for (int i = 0; i < 25; i++) w[i] = (i < ksz) ? wp[i] : 0.f;
    int py = tid >> 3, px0 = (tid & 7) * 4;
    float4 acc;
    int dil = da.dil[e];
    if (ks == 3 && dil == 1)      acc = dw_inner4<3,1,1>(st, w, py, px0);
    else if (ks == 5 && dil == 1) acc = dw_inner4<5,1,2>(st, w, py, px0);
    else if (ks == 3)             acc = dw_inner4<3,2,2>(st, w, py, px0);
    else                          acc = dw_inner4<5,2,4>(st, w, py, px0);
    float* yp = da.Y[e] + (long)b * PLANE + c * HW + py * 32 + px0;
    *(float4*)yp = acc;
}

// ---------------- tensor-core GEMM (bf16 hi/lo split, fp32 accumulate) ----------------
// C[128(M) x 1024(N)] = A[128 x K] * B[K x 1024] per (entry, batch).
// Block: 256 thr = 8 warps (4M x 2N), tile 128(M) x 128(N), k-step 16.
// Split: x = hi + lo (bf16); C += A_hi*B_hi + A_lo*B_hi + A_hi*B_lo.
// Double-buffered smem: one __syncthreads per k-step.
struct GemmArgs {
    const float* A[20];
    const float* B[20];
    float*       Cp[20];
    const float* P[20];
    float        cscale[20];
    int          byP[20];
    int          accum[20];
    long         bsB[20];
    long         bsC[20];
    int          K;
    int          reluB;
};

__device__ __forceinline__ void ldsm4(uint32_t* d, uint32_t addr) {
    asm volatile("ldmatrix.sync.aligned.m8n8.x4.shared.b16 {%0,%1,%2,%3}, [%4];"
                 : "=r"(d[0]), "=r"(d[1]), "=r"(d[2]), "=r"(d[3]) : "r"(addr));
}
__device__ __forceinline__ void ldsm4t(uint32_t* d, uint32_t addr) {
    asm volatile("ldmatrix.sync.aligned.m8n8.x4.trans.shared.b16 {%0,%1,%2,%3}, [%4];"
                 : "=r"(d[0]), "=r"(d[1]), "=r"(d[2]), "=r"(d[3]) : "r"(addr));
}
__device__ __forceinline__ void mma16816(float* c, const uint32_t* a,
                                         uint32_t b0, uint32_t b1) {
    asm volatile("mma.sync.aligned.m16n8k16.row.col.f32.bf16.bf16.f32 "
                 "{%0,%1,%2,%3}, {%4,%5,%6,%7}, {%8,%9}, {%0,%1,%2,%3};"
                 : "+f"(c[0]), "+f"(c[1]), "+f"(c[2]), "+f"(c[3])
                 : "r"(a[0]), "r"(a[1]), "r"(a[2]), "r"(a[3]), "r"(b0), "r"(b1));
}

#define A_LD 24    // halfs per A smem row (16 data + pad)
#define B_LD 136   // halfs per B smem row (128 data + pad)
#define ABUF_BYTES (2 * 128 * A_LD * 2)  // one buffer = both planes
#define BBUF_BYTES (2 * 16 * B_LD * 2)

__global__ __launch_bounds__(256) void gemm_mma(GemmArgs ga) {
    int e = blockIdx.z, b = blockIdx.y;
    const float* gp = ga.P[e];
    float pv = 1.f;
    if (gp) { pv = gp[b * 8]; if (pv == 0.f) return; }
    float scale = ga.cscale[e] * (ga.byP[e] ? pv : 1.f);
    const int K = ga.K;
    const int reluB = ga.reluB;

    // [buf][plane][row][ld]
    __shared__ __align__(16) __nv_bfloat16 As[2][2][128][A_LD];
    __shared__ __align__(16) __nv_bfloat16 Bs[2][2][16][B_LD];

    int tid  = threadIdx.x;
    int lane = tid & 31, w = tid >> 5;
    int wm = (w & 3) * 32;        // warp M origin
    int wn = (w >> 2) * 64;       // warp N origin

    int am = tid >> 1, ak = (tid & 1) * 8;     // A loader
    int bk = tid >> 4, bc = (tid & 15) * 8;    // B loader

    const float* Aptr = ga.A[e] + (long)am * K + ak;
    const float* Bptr = ga.B[e] + (long)b * ga.bsB[e] + blockIdx.x * 128
                        + (long)bk * HW + bc;
    float* Cm = ga.Cp[e] + (long)b * ga.bsC[e] + blockIdx.x * 128;

    int r8 = lane & 7, quad = lane >> 3;
    int lrow = r8 + (quad & 1) * 8;
    int lcol = (quad >> 1) * 8;

    uint32_t asBase = (uint32_t)__cvta_generic_to_shared(&As[0][0][0][0]);
    uint32_t bsBase = (uint32_t)__cvta_generic_to_shared(&Bs[0][0][0][0]);
    uint32_t aAddr[2][2], bAddr[2][4];   // buffer-0 addresses, [plane][...]
#pragma unroll
    for (int p = 0; p < 2; p++) {
#pragma unroll
        for (int mt = 0; mt < 2; mt++)
            aAddr[p][mt] = asBase + ((p * 128 + wm + mt * 16 + lrow) * A_LD + lcol) * 2;
#pragma unroll
        for (int i = 0; i < 4; i++)
            bAddr[p][i] = bsBase + ((p * 16 + lrow) * B_LD + wn + i * 16 + lcol) * 2;
    }

    float acc[2][8][4];
#pragma unroll
    for (int mt = 0; mt < 2; mt++)
#pragma unroll
        for (int nt = 0; nt < 8; nt++)
#pragma unroll
            for (int q = 0; q < 4; q++) acc[mt][nt][q] = 0.f;

    // prologue: fetch + convert tile 0 into buffer 0
    {
        float4 ra0 = *(const float4*)(Aptr);
        float4 ra1 = *(const float4*)(Aptr + 4);
        float4 rb0 = *(const float4*)(Bptr);
        float4 rb1 = *(const float4*)(Bptr + 4);
        if (reluB) { relu4(rb0); relu4(rb1); }
        uint32_t h0, h1, h2, h3, l0, l1, l2, l3;
        split4(ra0, h0, h1, l0, l1);
        split4(ra1, h2, h3, l2, l3);
        *(uint4*)&As[0][0][am][ak] = make_uint4(h0, h1, h2, h3);
        *(uint4*)&As[0][1][am][ak] = make_uint4(l0, l1, l2, l3);
        split4(rb0, h0, h1, l0, l1);
        split4(rb1, h2, h3, l2, l3);
        *(uint4*)&Bs[0][0][bk][bc] = make_uint4(h0, h1, h2, h3);
        *(uint4*)&Bs[0][1][bk][bc] = make_uint4(l0, l1, l2, l3);
    }
    __syncthreads();

    const int T = K >> 4;
    int cur = 0;
    for (int t = 0; t < T; t++) {
        bool more = (t + 1 < T);
        float4 ra0, ra1, rb0, rb1;
        if (more) {
            ra0 = *(const float4*)(Aptr + (t + 1) * 16);
            ra1 = *(const float4*)(Aptr + (t + 1) * 16 + 4);
            const float* bp = Bptr + (long)(t + 1) * 16 * HW;
            rb0 = *(const float4*)(bp);
            rb1 = *(const float4*)(bp + 4);
        }

        uint32_t offA = cur * ABUF_BYTES;
        uint32_t offB = cur * BBUF_BYTES;
        uint32_t afr[2][2][4];
        uint32_t bfr[2][4][4];
#pragma unroll
        for (int p = 0; p < 2; p++) {
#pragma unroll
            for (int mt = 0; mt < 2; mt++) ldsm4(afr[p][mt], aAddr[p][mt] + offA);
#pragma unroll
            for (int i = 0; i < 4; i++)    ldsm4t(bfr[p][i], bAddr[p][i] + offB);
        }
#pragma unroll
        for (int combo = 0; combo < 3; combo++) {
            int ap = (combo == 1) ? 1 : 0;
            int bp = (combo == 2) ? 1 : 0;
#pragma unroll
            for (int mt = 0; mt < 2; mt++)
#pragma unroll
                for (int nt = 0; nt < 8; nt++) {
                    int i = nt >> 1, po = (nt & 1) * 2;
                    mma16816(acc[mt][nt], afr[ap][mt], bfr[bp][i][po], bfr[bp][i][po + 1]);
                }
        }

        if (more) {
            int nxt = cur ^ 1;
            if (reluB) { relu4(rb0); relu4(rb1); }
            uint32_t h0, h1, h2, h3, l0, l1, l2, l3;
            split4(ra0, h0, h1, l0, l1);
            split4(ra1, h2, h3, l2, l3);
            *(uint4*)&As[nxt][0][am][ak] = make_uint4(h0, h1, h2, h3);
            *(uint4*)&As[nxt][1][am][ak] = make_uint4(l0, l1, l2, l3);
            split4(rb0, h0, h1, l0, l1);
            split4(rb1, h2, h3, l2, l3);
            *(uint4*)&Bs[nxt][0][bk][bc] = make_uint4(h0, h1, h2, h3);
            *(uint4*)&Bs[nxt][1][bk][bc] = make_uint4(l0, l1, l2, l3);
            __syncthreads();
            cur = nxt;
        }
    }

    // epilogue
    int g = lane >> 2, tig = lane & 3;
    if (ga.accum[e]) {
#pragma unroll
        for (int mt = 0; mt < 2; mt++)
#pragma unroll
            for (int nt = 0; nt < 8; nt++) {
                int row = wm + mt * 16 + g;
                int col = wn + nt * 8 + tig * 2;
                float* p0 = Cm + (long)row * HW + col;
                float* p1 = p0 + 8 * HW;
                atomicAdd(&p0[0], scale * acc[mt][nt][0]);
                atomicAdd(&p0[1], scale * acc[mt][nt][1]);
                atomicAdd(&p1[0], scale * acc[mt][nt][2]);
                atomicAdd(&p1[1], scale * acc[mt][nt][3]);
            }
    } else {
#pragma unroll
        for (int mt = 0; mt < 2; mt++)
#pragma unroll
            for (int nt = 0; nt < 8; nt++) {
                int row = wm + mt * 16 + g;
                int col = wn + nt * 8 + tig * 2;
                float* p0 = Cm + (long)row * HW + col;
                float* p1 = p0 + 8 * HW;
                *(float2*)p0 = make_float2(scale * acc[mt][nt][0], scale * acc[mt][nt][1]);
                *(float2*)p1 = make_float2(scale * acc[mt][nt][2], scale * acc[mt][nt][3]);
            }
    }
}

// ---------------- host orchestration ----------------
extern "C" void kernel_launch(void* const* d_in, const int* in_sizes, int n_in,
                              void* d_out, int out_size) {
    const float* s0r   = (const float*)d_in[0];
    const float* s1r   = (const float*)d_in[1];
    const float* gates = (const float*)d_in[2];
    const float* pre0  = (const float*)d_in[3];
    const float* pre1  = (const float*)d_in[4];
    const float* s3d1  = (const float*)d_in[5];
    const float* s3p1  = (const float*)d_in[6];
    const float* s3d2  = (const float*)d_in[7];
    const float* s3p2  = (const float*)d_in[8];
    const float* s5d1  = (const float*)d_in[9];
    const float* s5p1  = (const float*)d_in[10];
    const float* s5d2  = (const float*)d_in[11];
    const float* s5p2  = (const float*)d_in[12];
    const float* d3d   = (const float*)d_in[13];
    const float* d3p   = (const float*)d_in[14];
    const float* d5d   = (const float*)d_in[15];
    const float* d5p   = (const float*)d_in[16];
    float* out = (float*)d_out;

    float *ps0, *ps1, *pt, *pu, *pp;
    cudaGetSymbolAddress((void**)&ps0, g_s0);
    cudaGetSymbolAddress((void**)&ps1, g_s1);
    cudaGetSymbolAddress((void**)&pt,  g_t);
    cudaGetSymbolAddress((void**)&pu,  g_u);
    cudaGetSymbolAddress((void**)&pp,  g_pw);

    gate_kernel<<<2, 256>>>(gates, pp);

    // preprocess: s0/s1 -> states 0/1 (ReLU -> 1x1 conv 512->128 -> BN)
    {
        GemmArgs pa = {};
        pa.K = CIN; pa.reluB = 1;
        pa.A[0] = pre0; pa.B[0] = s0r; pa.Cp[0] = ps0; pa.P[0] = nullptr;
        pa.cscale[0] = BNS; pa.bsB[0] = (long)CIN * HW; pa.bsC[0] = PLANE;
        pa.A[1] = pre1; pa.B[1] = s1r; pa.Cp[1] = ps1; pa.P[1] = nullptr;
        pa.cscale[1] = BNS; pa.bsB[1] = (long)CIN * HW; pa.bsC[1] = PLANE;
        gemm_mma<<<dim3(8, NB, 2), 256>>>(pa);
    }

    struct StateDesc { float* p; long bs; };
    StateDesc st[6] = {
        {ps0, (long)PLANE}, {ps1, (long)PLANE},
        {out,             512L * HW}, {out + PLANE,     512L * HW},
        {out + 2 * PLANE, 512L * HW}, {out + 3 * PLANE, 512L * HW}
    };

    const float* dw1w[4]  = {s3d1, s5d1, d3d, d5d};
    const long   dw1sz[4] = {9, 25, 9, 25};
    const int    dwk[4]   = {3, 5, 3, 5};
    const int    dwdil[4] = {1, 1, 2, 2};
    const float* pw1w[4]  = {s3p1, s5p1, d3p, d5p};

    int offset = 0;
    for (int i = 0; i < 4; i++) {
        int nj = 2 + i;
        StateDesc dst = st[2 + i];

        // pools + skip, all j in one launch
        PoolArgs pa = {};
        for (int j = 0; j < nj; j++) {
            pa.X[j] = st[j].p; pa.bsX[j] = st[j].bs;
            pa.P[j] = pp + (long)(offset + j) * NB * 8;
        }
        pa.O = dst.p; pa.bsO = dst.bs; pa.nj = nj;
        pool_kernel<<<dim3(CC, NB), 256>>>(pa);

        // dw1: all (j, branch)
        DwArgs d1 = {};
        for (int j = 0; j < nj; j++) {
            int m = offset + j;
            const float* gp = pp + (long)m * NB * 8;
            for (int br = 0; br < 4; br++) {
                int e = j * 4 + br;
                d1.X[e] = st[j].p; d1.bsX[e] = st[j].bs;
                d1.W[e] = dw1w[br] + (long)m * CC * dw1sz[br];
                d1.Y[e] = pt + (long)e * NBPLANE;
                d1.P[e] = gp + 4 + br;
                d1.ks[e] = dwk[br]; d1.dil[e] = dwdil[br];
            }
        }
        dw_kernel<<<dim3(CC, NB, nj * 4), 256>>>(d1);

        // gemm1: sep pw1 -> u (store), dil pw -> dst (scaled atomic accumulate)
        GemmArgs g1 = {};
        g1.K = CC; g1.reluB = 0;
        for (int j = 0; j < nj; j++) {
            int m = offset + j;
            const float* gp = pp + (long)m * NB * 8;
            for (int br = 0; br < 4; br++) {
                int e = j * 4 + br;
                g1.A[e] = pw1w[br] + (long)m * CC * CC;
                g1.B[e] = pt + (long)e * NBPLANE;
                g1.P[e] = gp + 4 + br;
                g1.cscale[e] = BNS;
                g1.bsB[e] = PLANE;
                if (br < 2) {
                    g1.Cp[e] = pu + (long)(j * 2 + br) * NBPLANE;
                    g1.byP[e] = 0; g1.accum[e] = 0; g1.bsC[e] = PLANE;
                } else {
                    g1.Cp[e] = dst.p;
                    g1.byP[e] = 1; g1.accum[e] = 1; g1.bsC[e] = dst.bs;
                }
            }
        }
        gemm_mma<<<dim3(8, NB, nj * 4), 256>>>(g1);

        // dw2: sep3_dw2 / sep5_dw2 on relu(u); outputs alias pt slots (already consumed)
        DwArgs d2 = {};
        for (int j = 0; j < nj; j++) {
            int m = offset + j;
            const float* gp = pp + (long)m * NB * 8;
            for (int br = 0; br < 2; br++) {
                int e = j * 2 + br;
                d2.X[e] = pu + (long)e * NBPLANE; d2.bsX[e] = PLANE;
                d2.W[e] = (br == 0 ? s3d2 + (long)m * CC * 9 : s5d2 + (long)m * CC * 25);
                d2.Y[e] = pt + (long)(j * 4 + br) * NBPLANE;
                d2.P[e] = gp + 4 + br;
                d2.ks[e] = (br == 0 ? 3 : 5); d2.dil[e] = 1;
            }
        }
        dw_kernel<<<dim3(CC, NB, nj * 2), 256>>>(d2);

        // gemm2: sep pw2 -> dst (scaled atomic accumulate)
        GemmArgs g2 = {};
        g2.K = CC; g2.reluB = 0;
        for (int j = 0; j < nj; j++) {
            int m = offset + j;
            const float* gp = pp + (long)m * NB * 8;
            for (int br = 0; br < 2; br++) {
                int e = j * 2 + br;
                g2.A[e] = (br == 0 ? s3p2 + (long)m * CC * CC : s5p2 + (long)m * CC * CC);
                g2.B[e] = pt + (long)(j * 4 + br) * NBPLANE;
                g2.Cp[e] = dst.p;
                g2.P[e] = gp + 4 + br;
                g2.cscale[e] = BNS; g2.byP[e] = 1; g2.accum[e] = 1;
                g2.bsB[e] = PLANE; g2.bsC[e] = dst.bs;
            }
        }
        gemm_mma<<<dim3(8, NB, nj * 2), 256>>>(g2);

        offset += nj;
    }
}

// round 16
// speedup vs baseline: 1.2222x; 1.0170x over previous
#include <cuda_runtime.h>
#include <cuda_bf16.h>
#include <cstdint>

// ---------------- problem constants ----------------
#define NB    32          // batch
#define CC    128         // cell channels
#define CIN   512         // input channels
#define HW    1024        // 32*32
#define PLANE (CC*HW)     // 131072 per (batch, state)
#define NBPLANE (NB*PLANE)
#define NMIX  14
#define BNS   0.9999950000374997f   // 1/sqrt(1+1e-5)

// ---------------- device scratch (static, allocation-free) ----------------
__device__ __align__(16) float g_s0[NBPLANE];
__device__ __align__(16) float g_s1[NBPLANE];
__device__ __align__(16) float g_t[2][20L * NBPLANE];  // dw outputs, double-buffered by step parity
__device__ __align__(16) float g_u[10L * NBPLANE];     // sep pw1 outputs
__device__ __align__(16) float g_pw[NMIX * NB * 8];

// ---------------- bf16 split helpers ----------------
__device__ __forceinline__ uint32_t packbf2(float e0, float e1) {
    uint32_t r;
    asm("cvt.rn.bf16x2.f32 %0, %1, %2;" : "=r"(r) : "f"(e1), "f"(e0));
    return r;
}
__device__ __forceinline__ void split4(float4 v, uint32_t& h0, uint32_t& h1,
                                       uint32_t& l0, uint32_t& l1) {
    h0 = packbf2(v.x, v.y);
    h1 = packbf2(v.z, v.w);
    float rx = v.x - __uint_as_float(h0 << 16);
    float ry = v.y - __uint_as_float(h0 & 0xffff0000u);
    float rz = v.z - __uint_as_float(h1 << 16);
    float rw = v.w - __uint_as_float(h1 & 0xffff0000u);
    l0 = packbf2(rx, ry);
    l1 = packbf2(rz, rw);
}
__device__ __forceinline__ void relu4(float4& v) {
    v.x = fmaxf(v.x, 0.f); v.y = fmaxf(v.y, 0.f);
    v.z = fmaxf(v.z, 0.f); v.w = fmaxf(v.w, 0.f);
}

// ---------------- gate kernel: top-2 + masked softmax ----------------
__global__ void gate_kernel(const float* __restrict__ gates, float* __restrict__ P) {
    int idx = blockIdx.x * blockDim.x + threadIdx.x;
    if (idx >= NMIX * NB) return;
    const float* g = gates + idx * 8;
    float gv[8];
#pragma unroll
    for (int j = 0; j < 8; j++) gv[j] = g[j];
    bool sel[8] = {false, false, false, false, false, false, false, false};
    for (int t = 0; t < 2; t++) {      // top = 2 fixed by setup_inputs
        int best = -1; float bv = -3.4e38f;
#pragma unroll
        for (int j = 0; j < 8; j++)
            if (!sel[j] && gv[j] > bv) { bv = gv[j]; best = j; }
        sel[best] = true;
    }
    float mx = -3.4e38f;
#pragma unroll
    for (int j = 0; j < 8; j++) if (sel[j]) mx = fmaxf(mx, gv[j]);
    float e[8]; float s = 0.f;
#pragma unroll
    for (int j = 0; j < 8; j++) { e[j] = sel[j] ? expf(gv[j] - mx) : 0.f; s += e[j]; }
#pragma unroll
    for (int j = 0; j < 8; j++) P[idx * 8 + j] = e[j] / s;
}

// ---------------- fused pool/skip kernel (4 consecutive px per thread) ----------------
struct PoolArgs {
    const float* X[5]; long bsX[5];
    const float* P[5];
    float* O; long bsO;
    int nj;
};

__global__ __launch_bounds__(256) void pool_kernel(PoolArgs pa) {
    int c = blockIdx.x, b = blockIdx.y, tid = threadIdx.x;
    __shared__ float st[1024];
    int py = tid >> 3, px0 = (tid & 7) * 4;
    float acc0 = 0.f, acc1 = 0.f, acc2 = 0.f, acc3 = 0.f;
    for (int j = 0; j < pa.nj; j++) {
        const float* pj = pa.P[j] + b * 8;
        float p1 = pj[1], p2 = pj[2], p3 = pj[3];
        if (p1 == 0.f && p2 == 0.f && p3 == 0.f) continue;   // uniform over block
        __syncthreads();
        const float* xp = pa.X[j] + (long)b * pa.bsX[j] + c * HW;
        for (int i = tid; i < 1024; i += 256) st[i] = xp[i];
        __syncthreads();
        float mx0 = -3.4e38f, mx1 = -3.4e38f, mx2 = -3.4e38f, mx3 = -3.4e38f;
        float s0 = 0.f, s1 = 0.f, s2 = 0.f, s3 = 0.f;
        int rows = 0;
#pragma unroll
        for (int dy = -1; dy <= 1; dy++) {
            int yy = py + dy;
            if (yy < 0 || yy > 31) continue;
            rows++;
            const float* rp = st + yy * 32 + px0;
            float v0 = (px0 > 0)  ? rp[-1] : 0.f;
            float m0 = (px0 > 0)  ? v0 : -3.4e38f;
            float v1 = rp[0], v2 = rp[1], v3 = rp[2], v4 = rp[3];
            float v5 = (px0 < 28) ? rp[4] : 0.f;
            float m5 = (px0 < 28) ? v5 : -3.4e38f;
            s0 += v0 + v1 + v2;  s1 += v1 + v2 + v3;
            s2 += v2 + v3 + v4;  s3 += v3 + v4 + v5;
            mx0 = fmaxf(mx0, fmaxf(m0, fmaxf(v1, v2)));
            mx1 = fmaxf(mx1, fmaxf(v1, fmaxf(v2, v3)));
            mx2 = fmaxf(mx2, fmaxf(v2, fmaxf(v3, v4)));
            mx3 = fmaxf(mx3, fmaxf(v3, fmaxf(v4, m5)));
        }
        float c0 = (float)(rows * (3 - (px0 == 0)));
        float c12 = (float)(rows * 3);
        float c3 = (float)(rows * (3 - (px0 == 28)));
        const float* ctr = st + py * 32 + px0;
        acc0 += p1 * (BNS * mx0) + p2 * (BNS * (s0 / c0))  + p3 * ctr[0];
        acc1 += p1 * (BNS * mx1) + p2 * (BNS * (s1 / c12)) + p3 * ctr[1];
        acc2 += p1 * (BNS * mx2) + p2 * (BNS * (s2 / c12)) + p3 * ctr[2];
        acc3 += p1 * (BNS * mx3) + p2 * (BNS * (s3 / c3))  + p3 * ctr[3];
    }
    float* op = pa.O + (long)b * pa.bsO + c * HW + py * 32 + px0;
    *(float4*)op = make_float4(acc0, acc1, acc2, acc3);   // sole writer pre-GEMM
}

// ---------------- fused multi-entry depthwise conv (4 consecutive px, fp32 out) ----------------
struct DwArgs {
    const float* X[20]; long bsX[20];
    const float* W[20];
    float*       Y[20];
    const float* P[20];
    int ks[20], dil[20];
};

template<int KS, int DIL, int PAD>
__device__ __forceinline__ float4 dw_inner4(const float* __restrict__ st,
                                            const float* __restrict__ w,
                                            int py, int px0)
{
    const float* base = st + (py + 4 - PAD) * 40 + (px0 + 4 - PAD);
    float a0 = 0.f, a1 = 0.f, a2 = 0.f, a3 = 0.f;
#pragma unroll
    for (int i = 0; i < KS; i++) {
        const float* rp = base + i * DIL * 40;
        float r[(KS - 1) * DIL + 4];
#pragma unroll
        for (int cidx = 0; cidx < (KS - 1) * DIL + 4; cidx++) r[cidx] = rp[cidx];
#pragma unroll
        for (int j = 0; j < KS; j++) {
            float wv = w[i * KS + j];
            a0 += wv * r[j * DIL + 0];
            a1 += wv * r[j * DIL + 1];
            a2 += wv * r[j * DIL + 2];
            a3 += wv * r[j * DIL + 3];
        }
    }
    return make_float4(a0, a1, a2, a3);
}

__global__ __launch_bounds__(256) void dw_kernel(DwArgs da) {
    int e = blockIdx.z, b = blockIdx.y, c = blockIdx.x;
    if (da.P[e][b * 8] == 0.f) return;
    __shared__ float st[1600];  // 40x40, relu(x) with zero halo (max pad 4)
    int tid = threadIdx.x;
    for (int i = tid; i < 1600; i += 256) st[i] = 0.f;
    __syncthreads();
    const float* xp = da.X[e] + (long)b * da.bsX[e] + c * HW;
    for (int i = tid; i < 1024; i += 256) {
        int y = i >> 5, x = i & 31;
        st[(y + 4) * 40 + x + 4] = fmaxf(xp[i], 0.f);
    }
    __syncthreads();
    int ks = da.ks[e];
    int ksz = ks * ks;
    const float* wp = da.W[e] + c * ksz;
    float w[25];
#pragma unroll
    for (int i = 0; i < 25; i++) w[i] = (i < ksz) ? wp[i] : 0.f;
    int py = tid >> 3, px0 = (tid & 7) * 4;
    float4 acc;
    int dil = da.dil[e];
    if (ks == 3 && dil == 1)      acc = dw_inner4<3,1,1>(st, w, py, px0);
    else if (ks == 5 && dil == 1) acc = dw_inner4<5,1,2>(st, w, py, px0);
    else if (ks == 3)             acc = dw_inner4<3,2,2>(st, w, py, px0);
    else                          acc = dw_inner4<5,2,4>(st, w, py, px0);
    float* yp = da.Y[e] + (long)b * PLANE + c * HW + py * 32 + px0;
    *(float4*)yp = acc;
}

// ---------------- tensor-core GEMM (bf16 hi/lo split, fp32 accumulate) ----------------
struct GemmArgs {
    const float* A[20];
    const float* B[20];
    float*       Cp[20];
    const float* P[20];
    float        cscale[20];
    int          byP[20];
    int          accum[20];
    long         bsB[20];
    long         bsC[20];
    int          K;
    int          reluB;
};

__device__ __forceinline__ void ldsm4(uint32_t* d, uint32_t addr) {
    asm volatile("ldmatrix.sync.aligned.m8n8.x4.shared.b16 {%0,%1,%2,%3}, [%4];"
                 : "=r"(d[0]), "=r"(d[1]), "=r"(d[2]), "=r"(d[3]) : "r"(addr));
}
__device__ __forceinline__ void ldsm4t(uint32_t* d, uint32_t addr) {
    asm volatile("ldmatrix.sync.aligned.m8n8.x4.trans.shared.b16 {%0,%1,%2,%3}, [%4];"
                 : "=r"(d[0]), "=r"(d[1]), "=r"(d[2]), "=r"(d[3]) : "r"(addr));
}
__device__ __forceinline__ void mma16816(float* c, const uint32_t* a,
                                         uint32_t b0, uint32_t b1) {
    asm volatile("mma.sync.aligned.m16n8k16.row.col.f32.bf16.bf16.f32 "
                 "{%0,%1,%2,%3}, {%4,%5,%6,%7}, {%8,%9}, {%0,%1,%2,%3};"
                 : "+f"(c[0]), "+f"(c[1]), "+f"(c[2]), "+f"(c[3])
                 : "r"(a[0]), "r"(a[1]), "r"(a[2]), "r"(a[3]), "r"(b0), "r"(b1));
}

#define A_LD 24
#define B_LD 136
#define ABUF_BYTES (2 * 128 * A_LD * 2)
#define BBUF_BYTES (2 * 16 * B_LD * 2)

__global__ __launch_bounds__(256) void gemm_mma(GemmArgs ga) {
    int e = blockIdx.z, b = blockIdx.y;
    const float* gp = ga.P[e];
    float pv = 1.f;
    if (gp) { pv = gp[b * 8]; if (pv == 0.f) return; }
    float scale = ga.cscale[e] * (ga.byP[e] ? pv : 1.f);
    const int K = ga.K;
    const int reluB = ga.reluB;

    __shared__ __align__(16) __nv_bfloat16 As[2][2][128][A_LD];
    __shared__ __align__(16) __nv_bfloat16 Bs[2][2][16][B_LD];

    int tid  = threadIdx.x;
    int lane = tid & 31, w = tid >> 5;
    int wm = (w & 3) * 32;
    int wn = (w >> 2) * 64;

    int am = tid >> 1, ak = (tid & 1) * 8;
    int bk = tid >> 4, bc = (tid & 15) * 8;

    const float* Aptr = ga.A[e] + (long)am * K + ak;
    const float* Bptr = ga.B[e] + (long)b * ga.bsB[e] + blockIdx.x * 128
                        + (long)bk * HW + bc;
    float* Cm = ga.Cp[e] + (long)b * ga.bsC[e] + blockIdx.x * 128;

    int r8 = lane & 7, quad = lane >> 3;
    int lrow = r8 + (quad & 1) * 8;
    int lcol = (quad >> 1) * 8;

    uint32_t asBase = (uint32_t)__cvta_generic_to_shared(&As[0][0][0][0]);
    uint32_t bsBase = (uint32_t)__cvta_generic_to_shared(&Bs[0][0][0][0]);
    uint32_t aAddr[2][2], bAddr[2][4];
#pragma unroll
    for (int p = 0; p < 2; p++) {
#pragma unroll
        for (int mt = 0; mt < 2; mt++)
            aAddr[p][mt] = asBase + ((p * 128 + wm + mt * 16 + lrow) * A_LD + lcol) * 2;
#pragma unroll
        for (int i = 0; i < 4; i++)
            bAddr[p][i] = bsBase + ((p * 16 + lrow) * B_LD + wn + i * 16 + lcol) * 2;
    }

    float acc[2][8][4];
#pragma unroll
    for (int mt = 0; mt < 2; mt++)
#pragma unroll
        for (int nt = 0; nt < 8; nt++)
#pragma unroll
            for (int q = 0; q < 4; q++) acc[mt][nt][q] = 0.f;

    {
        float4 ra0 = *(const float4*)(Aptr);
        float4 ra1 = *(const float4*)(Aptr + 4);
        float4 rb0 = *(const float4*)(Bptr);
        float4 rb1 = *(const float4*)(Bptr + 4);
        if (reluB) { relu4(rb0); relu4(rb1); }
        uint32_t h0, h1, h2, h3, l0, l1, l2, l3;
        split4(ra0, h0, h1, l0, l1);
        split4(ra1, h2, h3, l2, l3);
        *(uint4*)&As[0][0][am][ak] = make_uint4(h0, h1, h2, h3);
        *(uint4*)&As[0][1][am][ak] = make_uint4(l0, l1, l2, l3);
        split4(rb0, h0, h1, l0, l1);
        split4(rb1, h2, h3, l2, l3);
        *(uint4*)&Bs[0][0][bk][bc] = make_uint4(h0, h1, h2, h3);
        *(uint4*)&Bs[0][1][bk][bc] = make_uint4(l0, l1, l2, l3);
    }
    __syncthreads();

    const int T = K >> 4;
    int cur = 0;
    for (int t = 0; t < T; t++) {
        bool more = (t + 1 < T);
        float4 ra0, ra1, rb0, rb1;
        if (more) {
            ra0 = *(const float4*)(Aptr + (t + 1) * 16);
            ra1 = *(const float4*)(Aptr + (t + 1) * 16 + 4);
            const float* bp = Bptr + (long)(t + 1) * 16 * HW;
            rb0 = *(const float4*)(bp);
            rb1 = *(const float4*)(bp + 4);
        }

        uint32_t offA = cur * ABUF_BYTES;
        uint32_t offB = cur * BBUF_BYTES;
        uint32_t afr[2][2][4];
        uint32_t bfr[2][4][4];
#pragma unroll
        for (int p = 0; p < 2; p++) {
#pragma unroll
            for (int mt = 0; mt < 2; mt++) ldsm4(afr[p][mt], aAddr[p][mt] + offA);
#pragma unroll
            for (int i = 0; i < 4; i++)    ldsm4t(bfr[p][i], bAddr[p][i] + offB);
        }
#pragma unroll
        for (int combo = 0; combo < 3; combo++) {
            int ap = (combo == 1) ? 1 : 0;
            int bp = (combo == 2) ? 1 : 0;
#pragma unroll
            for (int mt = 0; mt < 2; mt++)
#pragma unroll
                for (int nt = 0; nt < 8; nt++) {
                    int i = nt >> 1, po = (nt & 1) * 2;
                    mma16816(acc[mt][nt], afr[ap][mt], bfr[bp][i][po], bfr[bp][i][po + 1]);
                }
        }

        if (more) {
            int nxt = cur ^ 1;
            if (reluB) { relu4(rb0); relu4(rb1); }
            uint32_t h0, h1, h2, h3, l0, l1, l2, l3;
            split4(ra0, h0, h1, l0, l1);
            split4(ra1, h2, h3, l2, l3);
            *(uint4*)&As[nxt][0][am][ak] = make_uint4(h0, h1, h2, h3);
            *(uint4*)&As[nxt][1][am][ak] = make_uint4(l0, l1, l2, l3);
            split4(rb0, h0, h1, l0, l1);
            split4(rb1, h2, h3, l2, l3);
            *(uint4*)&Bs[nxt][0][bk][bc] = make_uint4(h0, h1, h2, h3);
            *(uint4*)&Bs[nxt][1][bk][bc] = make_uint4(l0, l1, l2, l3);
            __syncthreads();
            cur = nxt;
        }
    }

    int g = lane >> 2, tig = lane & 3;
    if (ga.accum[e]) {
#pragma unroll
        for (int mt = 0; mt < 2; mt++)
#pragma unroll
            for (int nt = 0; nt < 8; nt++) {
                int row = wm + mt * 16 + g;
                int col = wn + nt * 8 + tig * 2;
                float* p0 = Cm + (long)row * HW + col;
                float* p1 = p0 + 8 * HW;
                atomicAdd(&p0[0], scale * acc[mt][nt][0]);
                atomicAdd(&p0[1], scale * acc[mt][nt][1]);
                atomicAdd(&p1[0], scale * acc[mt][nt][2]);
                atomicAdd(&p1[1], scale * acc[mt][nt][3]);
            }
    } else {
#pragma unroll
        for (int mt = 0; mt < 2; mt++)
#pragma unroll
            for (int nt = 0; nt < 8; nt++) {
                int row = wm + mt * 16 + g;
                int col = wn + nt * 8 + tig * 2;
                float* p0 = Cm + (long)row * HW + col;
                float* p1 = p0 + 8 * HW;
                *(float2*)p0 = make_float2(scale * acc[mt][nt][0], scale * acc[mt][nt][1]);
                *(float2*)p1 = make_float2(scale * acc[mt][nt][2], scale * acc[mt][nt][3]);
            }
    }
}

// ---------------- persistent host objects (created once, outside capture) ----------------
static cudaStream_t s_sD = nullptr;
static cudaEvent_t  s_evPre = nullptr;
static cudaEvent_t  s_evReady[4], s_evDil[4], s_evState[6];

static void ensure_resources() {
    if (s_sD) return;
    cudaStreamCaptureStatus cs = cudaStreamCaptureStatusNone;
    cudaStreamIsCapturing((cudaStream_t)0, &cs);
    if (cs != cudaStreamCaptureStatusNone) return;   // never create during capture
    cudaStream_t tmp = nullptr;
    if (cudaStreamCreateWithFlags(&tmp, cudaStreamNonBlocking) != cudaSuccess) return;
    cudaEventCreateWithFlags(&s_evPre, cudaEventDisableTiming);
    for (int i = 0; i < 4; i++) {
        cudaEventCreateWithFlags(&s_evReady[i], cudaEventDisableTiming);
        cudaEventCreateWithFlags(&s_evDil[i], cudaEventDisableTiming);
    }
    for (int i = 0; i < 6; i++) cudaEventCreateWithFlags(&s_evState[i], cudaEventDisableTiming);
    s_sD = tmp;   // publish last
}

// ---------------- host orchestration (two-stream DAG; serial-safe fallback) ----------------
extern "C" void kernel_launch(void* const* d_in, const int* in_sizes, int n_in,
                              void* d_out, int out_size) {
    const float* s0r   = (const float*)d_in[0];
    const float* s1r   = (const float*)d_in[1];
    const float* gates = (const float*)d_in[2];
    const float* pre0  = (const float*)d_in[3];
    const float* pre1  = (const float*)d_in[4];
    const float* s3d1  = (const float*)d_in[5];
    const float* s3p1  = (const float*)d_in[6];
    const float* s3d2  = (const float*)d_in[7];
    const float* s3p2  = (const float*)d_in[8];
    const float* s5d1  = (const float*)d_in[9];
    const float* s5p1  = (const float*)d_in[10];
    const float* s5d2  = (const float*)d_in[11];
    const float* s5p2  = (const float*)d_in[12];
    const float* d3d   = (const float*)d_in[13];
    const float* d3p   = (const float*)d_in[14];
    const float* d5d   = (const float*)d_in[15];
    const float* d5p   = (const float*)d_in[16];
    float* out = (float*)d_out;

    ensure_resources();
    const bool ov = (s_sD != nullptr);               // overlap enabled
    cudaStream_t sD = ov ? s_sD : (cudaStream_t)0;   // fallback: serial on stream 0
    auto REC  = [&](cudaEvent_t e, cudaStream_t s) { if (ov) cudaEventRecord(e, s); };
    auto WAIT = [&](cudaStream_t s, cudaEvent_t e) { if (ov) cudaStreamWaitEvent(s, e, 0); };

    float *ps0, *ps1, *ptAll, *pu, *pp;
    cudaGetSymbolAddress((void**)&ps0, g_s0);
    cudaGetSymbolAddress((void**)&ps1, g_s1);
    cudaGetSymbolAddress((void**)&ptAll, g_t);
    cudaGetSymbolAddress((void**)&pu,  g_u);
    cudaGetSymbolAddress((void**)&pp,  g_pw);

    // ---- main stream: gate + preprocess ----
    gate_kernel<<<2, 256, 0, 0>>>(gates, pp);
    {
        GemmArgs pa = {};
        pa.K = CIN; pa.reluB = 1;
        pa.A[0] = pre0; pa.B[0] = s0r; pa.Cp[0] = ps0; pa.P[0] = nullptr;
        pa.cscale[0] = BNS; pa.bsB[0] = (long)CIN * HW; pa.bsC[0] = PLANE;
        pa.A[1] = pre1; pa.B[1] = s1r; pa.Cp[1] = ps1; pa.P[1] = nullptr;
        pa.cscale[1] = BNS; pa.bsB[1] = (long)CIN * HW; pa.bsC[1] = PLANE;
        gemm_mma<<<dim3(8, NB, 2), 256, 0, 0>>>(pa);
    }
    REC(s_evPre, 0);
    WAIT(sD, s_evPre);   // fork side stream

    struct StateDesc { float* p; long bs; };
    StateDesc st[6] = {
        {ps0, (long)PLANE}, {ps1, (long)PLANE},
        {out,             512L * HW}, {out + PLANE,     512L * HW},
        {out + 2 * PLANE, 512L * HW}, {out + 3 * PLANE, 512L * HW}
    };

    const float* dw1w[4]  = {s3d1, s5d1, d3d, d5d};
    const long   dw1sz[4] = {9, 25, 9, 25};
    const int    dwk[4]   = {3, 5, 3, 5};
    const int    dwdil[4] = {1, 1, 2, 2};
    const float* pw1w[4]  = {s3p1, s5p1, d3p, d5p};

    int offsets[4] = {0, 2, 5, 9};

    auto build_dw1 = [&](int i, int jlo, int jhi, DwArgs& d, int& cnt) {
        float* pt = ptAll + (long)(i & 1) * 20L * NBPLANE;
        cnt = 0;
        for (int j = jlo; j <= jhi; j++) {
            int m = offsets[i] + j;
            const float* gp = pp + (long)m * NB * 8;
            for (int br = 0; br < 4; br++) {
                int e = cnt++;
                d.X[e] = st[j].p; d.bsX[e] = st[j].bs;
                d.W[e] = dw1w[br] + (long)m * CC * dw1sz[br];
                d.Y[e] = pt + (long)(j * 4 + br) * NBPLANE;
                d.P[e] = gp + 4 + br;
                d.ks[e] = dwk[br]; d.dil[e] = dwdil[br];
            }
        }
    };

    for (int i = 0; i < 4; i++) {
        int nj = 2 + i;
        StateDesc dst = st[2 + i];
        float* pt = ptAll + (long)(i & 1) * 20L * NBPLANE;

        // ---------- side-stream block ----------
        if (i == 0) {
            DwArgs d; int cnt;
            build_dw1(0, 0, 1, d, cnt);   // step 0: all sources ready post-preprocess
            dw_kernel<<<dim3(CC, NB, cnt), 256, 0, sD>>>(d);
        } else {
            WAIT(sD, s_evState[1 + i]);   // newest source = state 1+i
            DwArgs d; int cnt;
            build_dw1(i, nj - 1, nj - 1, d, cnt);
            dw_kernel<<<dim3(CC, NB, cnt), 256, 0, sD>>>(d);
        }
        {
            PoolArgs pa = {};
            for (int j = 0; j < nj; j++) {
                pa.X[j] = st[j].p; pa.bsX[j] = st[j].bs;
                pa.P[j] = pp + (long)(offsets[i] + j) * NB * 8;
            }
            pa.O = dst.p; pa.bsO = dst.bs; pa.nj = nj;
            pool_kernel<<<dim3(CC, NB), 256, 0, sD>>>(pa);
        }
        REC(s_evReady[i], sD);

        // gemm1_dil on side stream (atomics into dst, after pool in-stream)
        {
            GemmArgs g = {};
            g.K = CC; g.reluB = 0;
            int cnt = 0;
            for (int j = 0; j < nj; j++) {
                int m = offsets[i] + j;
                const float* gp = pp + (long)m * NB * 8;
                for (int br = 2; br < 4; br++) {
                    int e = cnt++;
                    g.A[e] = pw1w[br] + (long)m * CC * CC;
                    g.B[e] = pt + (long)(j * 4 + br) * NBPLANE;
                    g.Cp[e] = dst.p;
                    g.P[e] = gp + 4 + br;
                    g.cscale[e] = BNS; g.byP[e] = 1; g.accum[e] = 1;
                    g.bsB[e] = PLANE; g.bsC[e] = dst.bs;
                }
            }
            gemm_mma<<<dim3(8, NB, cnt), 256, 0, sD>>>(g);
        }
        REC(s_evDil[i], sD);

        // dw1_old of NEXT step (sources are states <= i+1, all exist; other parity buffer)
        if (i < 3) {
            DwArgs d; int cnt;
            build_dw1(i + 1, 0, i + 1, d, cnt);
            dw_kernel<<<dim3(CC, NB, cnt), 256, 0, sD>>>(d);
        }

        // ---------- main-stream block ----------
        WAIT((cudaStream_t)0, s_evReady[i]);
        {
            GemmArgs g = {};
            g.K = CC; g.reluB = 0;
            int cnt = 0;
            for (int j = 0; j < nj; j++) {
                int m = offsets[i] + j;
                const float* gp = pp + (long)m * NB * 8;
                for (int br = 0; br < 2; br++) {
                    int e = cnt++;
                    g.A[e] = pw1w[br] + (long)m * CC * CC;
                    g.B[e] = pt + (long)(j * 4 + br) * NBPLANE;
                    g.Cp[e] = pu + (long)(j * 2 + br) * NBPLANE;
                    g.P[e] = gp + 4 + br;
                    g.cscale[e] = BNS; g.byP[e] = 0; g.accum[e] = 0;
                    g.bsB[e] = PLANE; g.bsC[e] = PLANE;
                }
            }
            gemm_mma<<<dim3(8, NB, cnt), 256, 0, 0>>>(g);
        }
        {
            DwArgs d = {};
            int cnt = 0;
            for (int j = 0; j < nj; j++) {
                int m = offsets[i] + j;
                const float* gp = pp + (long)m * NB * 8;
                for (int br = 0; br < 2; br++) {
                    int e = cnt++;
                    d.X[e] = pu + (long)(j * 2 + br) * NBPLANE; d.bsX[e] = PLANE;
                    d.W[e] = (br == 0 ? s3d2 + (long)m * CC * 9 : s5d2 + (long)m * CC * 25);
                    d.Y[e] = pt + (long)(j * 4 + br) * NBPLANE;
                    d.P[e] = gp + 4 + br;
                    d.ks[e] = (br == 0 ? 3 : 5); d.dil[e] = 1;
                }
            }
            dw_kernel<<<dim3(CC, NB, cnt), 256, 0, 0>>>(d);
        }
        {
            GemmArgs g = {};
            g.K = CC; g.reluB = 0;
            int cnt = 0;
            for (int j = 0; j < nj; j++) {
                int m = offsets[i] + j;
                const float* gp = pp + (long)m * NB * 8;
                for (int br = 0; br < 2; br++) {
                    int e = cnt++;
                    g.A[e] = (br == 0 ? s3p2 + (long)m * CC * CC : s5p2 + (long)m * CC * CC);
                    g.B[e] = pt + (long)(j * 4 + br) * NBPLANE;
                    g.Cp[e] = dst.p;
                    g.P[e] = gp + 4 + br;
                    g.cscale[e] = BNS; g.byP[e] = 1; g.accum[e] = 1;
                    g.bsB[e] = PLANE; g.bsC[e] = dst.bs;
                }
            }
            gemm_mma<<<dim3(8, NB, cnt), 256, 0, 0>>>(g);
        }
        WAIT((cudaStream_t)0, s_evDil[i]);   // join dil atomics
        REC(s_evState[2 + i], 0);            // state 2+i complete
    }
}